// round 17
// baseline (speedup 1.0000x reference)
#include <cuda_runtime.h>
#include <cuda_fp16.h>

#define NN 100000
#define EE 1600000
#define FIN 128
#define HID 64

// ---- scratch (static __device__ — no allocation) ----
__device__ __align__(16) __half2 g_h1h[NN * 32];  // h1, fp16, feature pairs (128B/row)
__device__ __align__(16) __half2 g_h2h[NN * 32];  // h2, fp16
__device__ __align__(16) float g_as1[NN * 4];
__device__ __align__(16) float g_ad1[NN * 4];
__device__ __align__(16) float g_agg1[NN * HID];
__device__ __align__(16) float g_as2[NN];
__device__ __align__(16) float g_ad2[NN];
__device__ int g_cnt[NN];    // degree by dst (zero at load; re-zeroed by agg2f each call)
__device__ int g_rs[NN];     // CSR row starts (unordered ranges)
__device__ int g_cur[NN];    // fill cursors
__device__ int g_srcs[EE];   // CSR: src per incident edge, grouped by dst
__device__ int g_total;      // range-allocation cursor (reset by k_fill each call)

__device__ __forceinline__ float lrelu(float t) { return fmaxf(t, 0.2f * t); }

// forced (non-hoistable) 16B global load
__device__ __forceinline__ float4 ldg128_volatile(const float* p) {
    float4 r;
    asm volatile("ld.global.nc.v4.f32 {%0,%1,%2,%3}, [%4];"
                 : "=f"(r.x), "=f"(r.y), "=f"(r.z), "=f"(r.w) : "l"(p));
    return r;
}

// ---------------- layer-1 GEMM (+ fused degree histogram), split-K warp pairs ----------------
__global__ void k_gemm1h(const float* __restrict__ x, const float* __restrict__ W1,
                         const float* __restrict__ a_src, const float* __restrict__ a_dst,
                         const int* __restrict__ ei) {
    __shared__ float2 Wsh[FIN * 32];                 // 32 KB
    __shared__ __align__(16) float Xbuf[4096];       // 16 KB: X staging, then combine buffer
    int tid = threadIdx.x;

    // fused histogram: exactly 2 edges per thread (3125*512 == EE)
    {
        int e = blockIdx.x * 512 + tid;
        atomicAdd(&g_cnt[__ldg(&ei[EE + e])], 1);
        atomicAdd(&g_cnt[__ldg(&ei[EE + e + 256])], 1);
    }

    for (int i = tid; i < FIN * 32; i += 256) Wsh[i] = ((const float2*)W1)[i];

    int lane = tid & 31, w = tid >> 5;
    int p = w >> 1, half = w & 1;
    int r0 = (blockIdx.x * 4 + p) * 8;

    float4* X = (float4*)Xbuf;   // X[(p*FIN + k)*2 + i]
#pragma unroll
    for (int kk = 0; kk < 2; kk++) {
        int k = half * 64 + kk * 32 + lane;
        float4 va, vb;
        va.x = x[(r0 + 0) * FIN + k];
        va.y = x[(r0 + 1) * FIN + k];
        va.z = x[(r0 + 2) * FIN + k];
        va.w = x[(r0 + 3) * FIN + k];
        vb.x = x[(r0 + 4) * FIN + k];
        vb.y = x[(r0 + 5) * FIN + k];
        vb.z = x[(r0 + 6) * FIN + k];
        vb.w = x[(r0 + 7) * FIN + k];
        X[(p * FIN + k) * 2 + 0] = va;
        X[(p * FIN + k) * 2 + 1] = vb;
    }
    __syncthreads();

    float acc0[8] = {}, acc1[8] = {};
    int kbase = half * 64;
#pragma unroll 16
    for (int kk = 0; kk < 64; kk++) {
        int k = kbase + kk;
        float4 xa = X[(p * FIN + k) * 2 + 0];
        float4 xb = X[(p * FIN + k) * 2 + 1];
        float2 wv = Wsh[k * 32 + lane];
        acc0[0] += xa.x * wv.x;  acc1[0] += xa.x * wv.y;
        acc0[1] += xa.y * wv.x;  acc1[1] += xa.y * wv.y;
        acc0[2] += xa.z * wv.x;  acc1[2] += xa.z * wv.y;
        acc0[3] += xa.w * wv.x;  acc1[3] += xa.w * wv.y;
        acc0[4] += xb.x * wv.x;  acc1[4] += xb.x * wv.y;
        acc0[5] += xb.y * wv.x;  acc1[5] += xb.y * wv.y;
        acc0[6] += xb.z * wv.x;  acc1[6] += xb.z * wv.y;
        acc0[7] += xb.w * wv.x;  acc1[7] += xb.w * wv.y;
    }
    __syncthreads();   // X staging no longer needed; reuse as combine buffer

    float* Cb = Xbuf;  // Cb[(p*16 + j)*32 + lane]
    if (half == 1) {
#pragma unroll
        for (int j = 0; j < 8; j++) {
            Cb[(p * 16 + j) * 32 + lane] = acc0[j];
            Cb[(p * 16 + 8 + j) * 32 + lane] = acc1[j];
        }
    }
    __syncthreads();

    if (half == 0) {
#pragma unroll
        for (int j = 0; j < 8; j++) {
            acc0[j] += Cb[(p * 16 + j) * 32 + lane];
            acc1[j] += Cb[(p * 16 + 8 + j) * 32 + lane];
        }
        float s0 = __ldg(&a_src[2 * lane]), s1 = __ldg(&a_src[2 * lane + 1]);
        float d0 = __ldg(&a_dst[2 * lane]), d1 = __ldg(&a_dst[2 * lane + 1]);
#pragma unroll
        for (int i = 0; i < 8; i++) {
            int row = r0 + i;
            g_h1h[row * 32 + lane] = __floats2half2_rn(acc0[i], acc1[i]);
            float pa = acc0[i] * s0 + acc1[i] * s1;
            float pd = acc0[i] * d0 + acc1[i] * d1;
#pragma unroll
            for (int off = 4; off; off >>= 1) {
                pa += __shfl_xor_sync(0xffffffffu, pa, off);
                pd += __shfl_xor_sync(0xffffffffu, pd, off);
            }
            if ((lane & 7) == 0) {
                g_as1[row * 4 + (lane >> 3)] = pa;
                g_ad1[row * 4 + (lane >> 3)] = pd;
            }
        }
    }
}

// ---------------- CSR range allocation ----------------
__global__ void k_alloc() {
    int i = blockIdx.x * blockDim.x + threadIdx.x;
    int lane = threadIdx.x & 31;
    int c = (i < NN) ? g_cnt[i] : 0;
    int s = c;
#pragma unroll
    for (int off = 1; off < 32; off <<= 1) {
        int t = __shfl_up_sync(0xffffffffu, s, off);
        if (lane >= off) s += t;
    }
    int wtot = __shfl_sync(0xffffffffu, s, 31);
    int base = 0;
    if (lane == 31) base = atomicAdd(&g_total, wtot);
    base = __shfl_sync(0xffffffffu, base, 31);
    if (i < NN) {
        int r = base + s - c;
        g_rs[i] = r;
        g_cur[i] = r;
    }
}

__global__ void k_fill(const int* __restrict__ ei) {
    int e = blockIdx.x * blockDim.x + threadIdx.x;
    if (e == 0) g_total = 0;
    if (e < EE) {
        int s = __ldg(&ei[e]);
        int d = __ldg(&ei[EE + e]);
        int p = atomicAdd(&g_cur[d], 1);
        g_srcs[p] = s;
    }
}

// ---------------- layer-1 gather aggregation: node-strided warps, header-prefetched ----------------
__global__ void k_agg1() {
    int lane = threadIdx.x & 31;
    int grp = lane >> 3;
    int q = lane & 7;
    int head = q >> 1;
    int wglob = blockIdx.x * 8 + (threadIdx.x >> 5);
    const int nwarps = 1250 * 8;

    const float4* h4 = (const float4*)g_h1h;

    int n = wglob;
    if (n >= NN) return;
    int rs = g_rs[n];
    int deg = g_cnt[n];
    float adv = g_ad1[n * 4 + head];

    while (n < NN) {
        // prefetch next node header under current node's edge loop
        int n2 = n + nwarps;
        int rs2 = 0, deg2 = 0;
        float adv2 = 0.f;
        if (n2 < NN) {
            rs2 = g_rs[n2];
            deg2 = g_cnt[n2];
            adv2 = g_ad1[n2 * 4 + head];
        }

        float a0 = 0.f, a1 = 0.f, a2 = 0.f, a3 = 0.f;
        float a4 = 0.f, a5 = 0.f, a6 = 0.f, a7 = 0.f, den = 0.f;

        for (int j = 0; j < deg; j += 8) {
            int j0 = j + grp, j1 = j + grp + 4;
            int s0 = g_srcs[rs + (j0 < deg ? j0 : deg - 1)];
            int s1 = g_srcs[rs + (j1 < deg ? j1 : deg - 1)];
            float c0 = g_as1[s0 * 4 + head];
            float c1 = g_as1[s1 * 4 + head];
            float4 r0 = h4[s0 * 8 + q];
            float4 r1 = h4[s1 * 8 + q];
            float e0 = (j0 < deg) ? __expf(lrelu(c0 + adv)) : 0.f;
            float e1 = (j1 < deg) ? __expf(lrelu(c1 + adv)) : 0.f;
            den += e0 + e1;
            const __half2* p0 = (const __half2*)&r0;
            const __half2* p1 = (const __half2*)&r1;
            float2 v;
            v = __half22float2(p0[0]); a0 += e0 * v.x; a1 += e0 * v.y;
            v = __half22float2(p0[1]); a2 += e0 * v.x; a3 += e0 * v.y;
            v = __half22float2(p0[2]); a4 += e0 * v.x; a5 += e0 * v.y;
            v = __half22float2(p0[3]); a6 += e0 * v.x; a7 += e0 * v.y;
            v = __half22float2(p1[0]); a0 += e1 * v.x; a1 += e1 * v.y;
            v = __half22float2(p1[1]); a2 += e1 * v.x; a3 += e1 * v.y;
            v = __half22float2(p1[2]); a4 += e1 * v.x; a5 += e1 * v.y;
            v = __half22float2(p1[3]); a6 += e1 * v.x; a7 += e1 * v.y;
        }
#pragma unroll
        for (int off = 8; off <= 16; off <<= 1) {
            den += __shfl_xor_sync(0xffffffffu, den, off);
            a0 += __shfl_xor_sync(0xffffffffu, a0, off);
            a1 += __shfl_xor_sync(0xffffffffu, a1, off);
            a2 += __shfl_xor_sync(0xffffffffu, a2, off);
            a3 += __shfl_xor_sync(0xffffffffu, a3, off);
            a4 += __shfl_xor_sync(0xffffffffu, a4, off);
            a5 += __shfl_xor_sync(0xffffffffu, a5, off);
            a6 += __shfl_xor_sync(0xffffffffu, a6, off);
            a7 += __shfl_xor_sync(0xffffffffu, a7, off);
        }
        float inv = 1.f / (den + 1e-16f);
        if (grp == 0) {
            float4* dst = (float4*)g_agg1 + n * 16 + q * 2;
            float4 o;
            o.x = a0 * inv; o.y = a1 * inv; o.z = a2 * inv; o.w = a3 * inv;
            dst[0] = o;
            o.x = a4 * inv; o.y = a5 * inv; o.z = a6 * inv; o.w = a7 * inv;
            dst[1] = o;
        }
        n = n2; rs = rs2; deg = deg2; adv = adv2;
    }
}

// ---------------- layer-2 GEMM: split-K warp pairs ----------------
__global__ void k_gemm2(const float* __restrict__ W2, const float* __restrict__ b1,
                        const float* __restrict__ a_src, const float* __restrict__ a_dst) {
    __shared__ float2 Wsh[HID * 32];                 // 16 KB
    __shared__ __align__(16) float Xbuf[2048];       // 8 KB
    int tid = threadIdx.x;
    for (int i = tid; i < HID * 32; i += 256) Wsh[i] = ((const float2*)W2)[i];

    int lane = tid & 31, w = tid >> 5;
    int p = w >> 1, half = w & 1;
    int r0 = (blockIdx.x * 4 + p) * 8;

    float4* X = (float4*)Xbuf;
    {
        int k = half * 32 + lane;
        float bk = __ldg(&b1[k]);
        float4 va, vb;
        va.x = fmaxf(g_agg1[(r0 + 0) * HID + k] + bk, 0.f);
        va.y = fmaxf(g_agg1[(r0 + 1) * HID + k] + bk, 0.f);
        va.z = fmaxf(g_agg1[(r0 + 2) * HID + k] + bk, 0.f);
        va.w = fmaxf(g_agg1[(r0 + 3) * HID + k] + bk, 0.f);
        vb.x = fmaxf(g_agg1[(r0 + 4) * HID + k] + bk, 0.f);
        vb.y = fmaxf(g_agg1[(r0 + 5) * HID + k] + bk, 0.f);
        vb.z = fmaxf(g_agg1[(r0 + 6) * HID + k] + bk, 0.f);
        vb.w = fmaxf(g_agg1[(r0 + 7) * HID + k] + bk, 0.f);
        X[(p * HID + k) * 2 + 0] = va;
        X[(p * HID + k) * 2 + 1] = vb;
    }
    __syncthreads();

    float acc0[8] = {}, acc1[8] = {};
    int kbase = half * 32;
#pragma unroll 8
    for (int kk = 0; kk < 32; kk++) {
        int k = kbase + kk;
        float4 xa = X[(p * HID + k) * 2 + 0];
        float4 xb = X[(p * HID + k) * 2 + 1];
        float2 wv = Wsh[k * 32 + lane];
        acc0[0] += xa.x * wv.x;  acc1[0] += xa.x * wv.y;
        acc0[1] += xa.y * wv.x;  acc1[1] += xa.y * wv.y;
        acc0[2] += xa.z * wv.x;  acc1[2] += xa.z * wv.y;
        acc0[3] += xa.w * wv.x;  acc1[3] += xa.w * wv.y;
        acc0[4] += xb.x * wv.x;  acc1[4] += xb.x * wv.y;
        acc0[5] += xb.y * wv.x;  acc1[5] += xb.y * wv.y;
        acc0[6] += xb.z * wv.x;  acc1[6] += xb.z * wv.y;
        acc0[7] += xb.w * wv.x;  acc1[7] += xb.w * wv.y;
    }
    __syncthreads();

    float* Cb = Xbuf;
    if (half == 1) {
#pragma unroll
        for (int j = 0; j < 8; j++) {
            Cb[(p * 16 + j) * 32 + lane] = acc0[j];
            Cb[(p * 16 + 8 + j) * 32 + lane] = acc1[j];
        }
    }
    __syncthreads();

    if (half == 0) {
#pragma unroll
        for (int j = 0; j < 8; j++) {
            acc0[j] += Cb[(p * 16 + j) * 32 + lane];
            acc1[j] += Cb[(p * 16 + 8 + j) * 32 + lane];
        }
        float s0 = __ldg(&a_src[2 * lane]), s1 = __ldg(&a_src[2 * lane + 1]);
        float d0 = __ldg(&a_dst[2 * lane]), d1 = __ldg(&a_dst[2 * lane + 1]);
#pragma unroll
        for (int i = 0; i < 8; i++) {
            int row = r0 + i;
            g_h2h[row * 32 + lane] = __floats2half2_rn(acc0[i], acc1[i]);
            float pa = acc0[i] * s0 + acc1[i] * s1;
            float pd = acc0[i] * d0 + acc1[i] * d1;
#pragma unroll
            for (int off = 16; off; off >>= 1) {
                pa += __shfl_xor_sync(0xffffffffu, pa, off);
                pd += __shfl_xor_sync(0xffffffffu, pd, off);
            }
            if (lane == 0) {
                g_as2[row] = pa;
                g_ad2[row] = pd;
            }
        }
    }
}

// ---------------- layer-2 gather aggregation + projection: node-strided, header-prefetched ----------------
__global__ void k_agg2f(const float* __restrict__ b2, const float* __restrict__ Wc,
                        const float* __restrict__ bc, float* __restrict__ out) {
    int lane = threadIdx.x & 31;
    int grp = lane >> 3;
    int q = lane & 7;
    int wglob = blockIdx.x * 8 + (threadIdx.x >> 5);
    const int nwarps = 1250 * 8;

    const float4* h4 = (const float4*)g_h2h;

    int n = wglob;
    if (n >= NN) return;
    int rs = g_rs[n];
    int deg = g_cnt[n];
    float adv = g_ad2[n];

    while (n < NN) {
        int n2 = n + nwarps;
        int rs2 = 0, deg2 = 0;
        float adv2 = 0.f;
        if (n2 < NN) {
            rs2 = g_rs[n2];
            deg2 = g_cnt[n2];
            adv2 = g_ad2[n2];
        }

        float a0 = 0.f, a1 = 0.f, a2 = 0.f, a3 = 0.f;
        float a4 = 0.f, a5 = 0.f, a6 = 0.f, a7 = 0.f, den = 0.f;

        for (int j = 0; j < deg; j += 8) {
            int j0 = j + grp, j1 = j + grp + 4;
            int s0 = g_srcs[rs + (j0 < deg ? j0 : deg - 1)];
            int s1 = g_srcs[rs + (j1 < deg ? j1 : deg - 1)];
            float c0 = g_as2[s0];
            float c1 = g_as2[s1];
            float4 r0 = h4[s0 * 8 + q];
            float4 r1 = h4[s1 * 8 + q];
            float e0 = (j0 < deg) ? __expf(lrelu(c0 + adv)) : 0.f;
            float e1 = (j1 < deg) ? __expf(lrelu(c1 + adv)) : 0.f;
            den += e0 + e1;
            const __half2* p0 = (const __half2*)&r0;
            const __half2* p1 = (const __half2*)&r1;
            float2 v;
            v = __half22float2(p0[0]); a0 += e0 * v.x; a1 += e0 * v.y;
            v = __half22float2(p0[1]); a2 += e0 * v.x; a3 += e0 * v.y;
            v = __half22float2(p0[2]); a4 += e0 * v.x; a5 += e0 * v.y;
            v = __half22float2(p0[3]); a6 += e0 * v.x; a7 += e0 * v.y;
            v = __half22float2(p1[0]); a0 += e1 * v.x; a1 += e1 * v.y;
            v = __half22float2(p1[1]); a2 += e1 * v.x; a3 += e1 * v.y;
            v = __half22float2(p1[2]); a4 += e1 * v.x; a5 += e1 * v.y;
            v = __half22float2(p1[3]); a6 += e1 * v.x; a7 += e1 * v.y;
        }
#pragma unroll
        for (int off = 8; off <= 16; off <<= 1) {
            den += __shfl_xor_sync(0xffffffffu, den, off);
            a0 += __shfl_xor_sync(0xffffffffu, a0, off);
            a1 += __shfl_xor_sync(0xffffffffu, a1, off);
            a2 += __shfl_xor_sync(0xffffffffu, a2, off);
            a3 += __shfl_xor_sync(0xffffffffu, a3, off);
            a4 += __shfl_xor_sync(0xffffffffu, a4, off);
            a5 += __shfl_xor_sync(0xffffffffu, a5, off);
            a6 += __shfl_xor_sync(0xffffffffu, a6, off);
            a7 += __shfl_xor_sync(0xffffffffu, a7, off);
        }
        float inv = 1.f / (den + 1e-16f);
        float4 ba = ldg128_volatile(b2 + q * 8);
        float4 bb = ldg128_volatile(b2 + q * 8 + 4);
        float4 wa = ldg128_volatile(Wc + q * 8);
        float4 wb = ldg128_volatile(Wc + q * 8 + 4);
        float v = fmaxf(a0 * inv + ba.x, 0.f) * wa.x
                + fmaxf(a1 * inv + ba.y, 0.f) * wa.y
                + fmaxf(a2 * inv + ba.z, 0.f) * wa.z
                + fmaxf(a3 * inv + ba.w, 0.f) * wa.w
                + fmaxf(a4 * inv + bb.x, 0.f) * wb.x
                + fmaxf(a5 * inv + bb.y, 0.f) * wb.y
                + fmaxf(a6 * inv + bb.z, 0.f) * wb.z
                + fmaxf(a7 * inv + bb.w, 0.f) * wb.w;
#pragma unroll
        for (int off = 1; off <= 4; off <<= 1) v += __shfl_xor_sync(0xffffffffu, v, off);
        if (lane == 0) {
            out[n] = v + __ldg(&bc[0]);
            g_cnt[n] = 0;  // restore invariant for next call's histogram
        }
        n = n2; rs = rs2; deg = deg2; adv = adv2;
    }
}

extern "C" void kernel_launch(void* const* d_in, const int* in_sizes, int n_in,
                              void* d_out, int out_size) {
    const float* x      = (const float*)d_in[0];
    const int* ei       = (const int*)d_in[1];   // JAX x64 disabled -> int32
    const float* W1     = (const float*)d_in[2];
    const float* a_src1 = (const float*)d_in[3];
    const float* a_dst1 = (const float*)d_in[4];
    const float* b1     = (const float*)d_in[5];
    const float* W2     = (const float*)d_in[6];
    const float* a_src2 = (const float*)d_in[7];
    const float* a_dst2 = (const float*)d_in[8];
    const float* b2     = (const float*)d_in[9];
    const float* Wc     = (const float*)d_in[10];
    const float* bc     = (const float*)d_in[11];
    float* out          = (float*)d_out;
    (void)in_sizes; (void)n_in; (void)out_size;

    k_gemm1h<<<3125, 256>>>(x, W1, a_src1, a_dst1, ei);  // 1: GEMM1 + degree hist
    k_alloc<<<(NN + 255) / 256, 256>>>();                // 2: CSR range alloc
    k_fill<<<(EE + 255) / 256, 256>>>(ei);               // 3: CSR fill
    k_agg1<<<1250, 256>>>();                             // 4: <- ncu sample
    k_gemm2<<<3125, 256>>>(W2, b1, a_src2, a_dst2);      // 5
    k_agg2f<<<1250, 256>>>(b2, Wc, bc, out);             // 6
}